// round 2
// baseline (speedup 1.0000x reference)
#include <cuda_runtime.h>
#include <math.h>

// Problem constants (fixed by the reference)
#define BATCH 4
#define SEQ   2048
#define DIM   1024   // D_IN == D_OUT == 1024

// GEMM tiling
#define BM 128
#define BN 128
#define BK 16
#define TM 8
#define TN 8
#define NTHREADS 256   // (BM/TM)*(BN/TN)

// ---------------------------------------------------------------------------
// Scratch (static device globals; no runtime allocation)
// ---------------------------------------------------------------------------
__device__ float g_q[(size_t)BATCH * SEQ * DIM];
__device__ float g_k[(size_t)BATCH * SEQ * DIM];
__device__ float g_v[(size_t)BATCH * SEQ * DIM];
__device__ float g_s[(size_t)BATCH * SEQ * SEQ];

// ---------------------------------------------------------------------------
// NT GEMM body, double-buffered: C[m,n] = alpha * sum_k A[m,k] * B[n,k]
// A: [M x K] row-major, B: [N x K] row-major, C row-major with leading dim Nld.
// All dims multiples of tile sizes (true for every call site here).
// ---------------------------------------------------------------------------
__device__ __forceinline__ void gemm_nt_body(
    const float* __restrict__ A, const float* __restrict__ Bp,
    float* __restrict__ C, int K, int Nld, float alpha, int bx, int by)
{
    __shared__ __align__(16) float As[2][BK][BM + 4];
    __shared__ __align__(16) float Bs[2][BK][BN + 4];

    const int tid  = threadIdx.x;
    const int row0 = (tid >> 4) * TM;
    const int col0 = (tid & 15) * TN;
    const int aRow = by * BM;
    const int bRow = bx * BN;

    // Per-thread global-load coordinates (2 float4 for A, 2 for B per tile)
    int fr[2], fc[2];
#pragma unroll
    for (int it = 0; it < 2; it++) {
        int f  = tid + it * NTHREADS;   // 0..511
        fr[it] = f >> 2;                // tile row 0..127
        fc[it] = (f & 3) * 4;           // k offset 0/4/8/12
    }

    float acc[TM][TN];
#pragma unroll
    for (int i = 0; i < TM; i++)
#pragma unroll
        for (int j = 0; j < TN; j++) acc[i][j] = 0.0f;

    float4 ra[2], rb[2];

    // ---- prologue: load tile k0=0 into regs, stage to buffer 0 ----
#pragma unroll
    for (int it = 0; it < 2; it++) {
        ra[it] = *(const float4*)(A  + (size_t)(aRow + fr[it]) * K + fc[it]);
        rb[it] = *(const float4*)(Bp + (size_t)(bRow + fr[it]) * K + fc[it]);
    }
#pragma unroll
    for (int it = 0; it < 2; it++) {
        As[0][fc[it] + 0][fr[it]] = ra[it].x; As[0][fc[it] + 1][fr[it]] = ra[it].y;
        As[0][fc[it] + 2][fr[it]] = ra[it].z; As[0][fc[it] + 3][fr[it]] = ra[it].w;
        Bs[0][fc[it] + 0][fr[it]] = rb[it].x; Bs[0][fc[it] + 1][fr[it]] = rb[it].y;
        Bs[0][fc[it] + 2][fr[it]] = rb[it].z; Bs[0][fc[it] + 3][fr[it]] = rb[it].w;
    }
    __syncthreads();

    int buf = 0;
    for (int k0 = BK; k0 < K; k0 += BK) {
        // prefetch next tile into registers (latency covered by compute below)
#pragma unroll
        for (int it = 0; it < 2; it++) {
            ra[it] = *(const float4*)(A  + (size_t)(aRow + fr[it]) * K + k0 + fc[it]);
            rb[it] = *(const float4*)(Bp + (size_t)(bRow + fr[it]) * K + k0 + fc[it]);
        }

        // compute current buffer
#pragma unroll
        for (int kk = 0; kk < BK; kk++) {
            float a[TM], b[TN];
            *(float4*)&a[0] = *(const float4*)&As[buf][kk][row0];
            *(float4*)&a[4] = *(const float4*)&As[buf][kk][row0 + 4];
            *(float4*)&b[0] = *(const float4*)&Bs[buf][kk][col0];
            *(float4*)&b[4] = *(const float4*)&Bs[buf][kk][col0 + 4];
#pragma unroll
            for (int i = 0; i < TM; i++)
#pragma unroll
                for (int j = 0; j < TN; j++) acc[i][j] += a[i] * b[j];
        }

        // stage prefetched tile into the other buffer
        const int nb = buf ^ 1;
#pragma unroll
        for (int it = 0; it < 2; it++) {
            As[nb][fc[it] + 0][fr[it]] = ra[it].x; As[nb][fc[it] + 1][fr[it]] = ra[it].y;
            As[nb][fc[it] + 2][fr[it]] = ra[it].z; As[nb][fc[it] + 3][fr[it]] = ra[it].w;
            Bs[nb][fc[it] + 0][fr[it]] = rb[it].x; Bs[nb][fc[it] + 1][fr[it]] = rb[it].y;
            Bs[nb][fc[it] + 2][fr[it]] = rb[it].z; Bs[nb][fc[it] + 3][fr[it]] = rb[it].w;
        }
        __syncthreads();      // single barrier per tile
        buf = nb;
    }

    // epilogue compute on last buffer
#pragma unroll
    for (int kk = 0; kk < BK; kk++) {
        float a[TM], b[TN];
        *(float4*)&a[0] = *(const float4*)&As[buf][kk][row0];
        *(float4*)&a[4] = *(const float4*)&As[buf][kk][row0 + 4];
        *(float4*)&b[0] = *(const float4*)&Bs[buf][kk][col0];
        *(float4*)&b[4] = *(const float4*)&Bs[buf][kk][col0 + 4];
#pragma unroll
        for (int i = 0; i < TM; i++)
#pragma unroll
            for (int j = 0; j < TN; j++) acc[i][j] += a[i] * b[j];
    }

    // write back
#pragma unroll
    for (int i = 0; i < TM; i++) {
        float* cp = C + (size_t)(aRow + row0 + i) * Nld + bx * BN + col0;
        *(float4*)(cp)     = make_float4(acc[i][0] * alpha, acc[i][1] * alpha,
                                         acc[i][2] * alpha, acc[i][3] * alpha);
        *(float4*)(cp + 4) = make_float4(acc[i][4] * alpha, acc[i][5] * alpha,
                                         acc[i][6] * alpha, acc[i][7] * alpha);
    }
}

// ---------------------------------------------------------------------------
// Kernel 1: fused QKV projection (one launch, blockIdx.z selects Wq/Wk/Wv)
// ---------------------------------------------------------------------------
__global__ void __launch_bounds__(NTHREADS, 2)
qkv_gemm_kernel(const float* __restrict__ X,
                const float* __restrict__ Wq,
                const float* __restrict__ Wk,
                const float* __restrict__ Wv)
{
    const float* W = (blockIdx.z == 0) ? Wq : (blockIdx.z == 1) ? Wk : Wv;
    float* C       = (blockIdx.z == 0) ? g_q : (blockIdx.z == 1) ? g_k : g_v;
    gemm_nt_body(X, W, C, DIM, DIM, 1.0f, blockIdx.x, blockIdx.y);
}

// ---------------------------------------------------------------------------
// Kernel 2: S[b] = (1/32) * Q[b] @ K[b]^T, fully-masked blocks skipped
// ---------------------------------------------------------------------------
__global__ void __launch_bounds__(NTHREADS, 2)
scores_gemm_kernel()
{
    if ((int)blockIdx.x > (int)blockIdx.y) return;   // strictly upper block: masked
    const int b = blockIdx.z;
    const float* Q  = g_q + (size_t)b * SEQ * DIM;
    const float* Kp = g_k + (size_t)b * SEQ * DIM;
    float* S        = g_s + (size_t)b * SEQ * SEQ;
    gemm_nt_body(Q, Kp, S, DIM, SEQ, 1.0f / 32.0f, blockIdx.x, blockIdx.y);
}

// ---------------------------------------------------------------------------
// Kernel 3: causal row softmax in place; zero-fill tail to 128-block boundary
// so the PV GEMM can run full-width K tiles up to the causal block edge.
// ---------------------------------------------------------------------------
__global__ void __launch_bounds__(NTHREADS)
softmax_kernel()
{
    const int row = blockIdx.x;           // 0 .. BATCH*SEQ-1
    const int i   = row & (SEQ - 1);      // query index within batch
    float* s = g_s + (size_t)row * SEQ;
    const int len = i + 1;
    const int tid = threadIdx.x;

    __shared__ float red[NTHREADS];

    float m = -1e30f;
    for (int j = tid; j < len; j += NTHREADS) m = fmaxf(m, s[j]);
    red[tid] = m; __syncthreads();
    for (int st = NTHREADS / 2; st > 0; st >>= 1) {
        if (tid < st) red[tid] = fmaxf(red[tid], red[tid + st]);
        __syncthreads();
    }
    m = red[0];
    __syncthreads();

    float sum = 0.0f;
    for (int j = tid; j < len; j += NTHREADS) {
        float e = expf(s[j] - m);
        s[j] = e;
        sum += e;
    }
    red[tid] = sum; __syncthreads();
    for (int st = NTHREADS / 2; st > 0; st >>= 1) {
        if (tid < st) red[tid] += red[tid + st];
        __syncthreads();
    }
    const float inv = 1.0f / red[0];
    __syncthreads();

    const int lenPad = ((i >> 7) + 1) << 7;   // next multiple of 128 above i
    for (int j = tid; j < lenPad; j += NTHREADS)
        s[j] = (j < len) ? s[j] * inv : 0.0f;
}

// ---------------------------------------------------------------------------
// Kernel 4: O[b] = P[b] @ V[b]  (NN GEMM, double-buffered, K truncated at
// the causal block boundary kend = (by+1)*128)
// ---------------------------------------------------------------------------
__global__ void __launch_bounds__(NTHREADS, 2)
pv_gemm_kernel(float* __restrict__ Out)
{
    const int b  = blockIdx.z;
    const int bx = blockIdx.x;
    const int by = blockIdx.y;
    const float* A  = g_s + (size_t)b * SEQ * SEQ;   // probs [SEQ x SEQ]
    const float* Bp = g_v + (size_t)b * SEQ * DIM;   // V [SEQ x DIM]
    float* C        = Out + (size_t)b * SEQ * DIM;

    __shared__ __align__(16) float As[2][BK][BM + 4];
    __shared__ __align__(16) float Bs[2][BK][BN];

    const int tid  = threadIdx.x;
    const int row0 = (tid >> 4) * TM;
    const int col0 = (tid & 15) * TN;
    const int aRow = by * BM;
    const int kend = (by + 1) * BM;

    int fr[2], fc[2], rb_[2], cb_[2];
#pragma unroll
    for (int it = 0; it < 2; it++) {
        int f   = tid + it * NTHREADS;
        fr[it]  = f >> 2;          // A tile row 0..127
        fc[it]  = (f & 3) * 4;     // A k offset
        rb_[it] = f >> 5;          // B k-row 0..15
        cb_[it] = (f & 31) * 4;    // B n offset 0..124
    }

    float acc[TM][TN];
#pragma unroll
    for (int i = 0; i < TM; i++)
#pragma unroll
        for (int j = 0; j < TN; j++) acc[i][j] = 0.0f;

    float4 ra[2], rbv[2];

    // prologue: tile 0
#pragma unroll
    for (int it = 0; it < 2; it++) {
        ra[it]  = *(const float4*)(A  + (size_t)(aRow + fr[it]) * SEQ + fc[it]);
        rbv[it] = *(const float4*)(Bp + (size_t)rb_[it] * DIM + bx * BN + cb_[it]);
    }
#pragma unroll
    for (int it = 0; it < 2; it++) {
        As[0][fc[it] + 0][fr[it]] = ra[it].x; As[0][fc[it] + 1][fr[it]] = ra[it].y;
        As[0][fc[it] + 2][fr[it]] = ra[it].z; As[0][fc[it] + 3][fr[it]] = ra[it].w;
        *(float4*)&Bs[0][rb_[it]][cb_[it]] = rbv[it];
    }
    __syncthreads();

    int buf = 0;
    for (int k0 = BK; k0 < kend; k0 += BK) {
#pragma unroll
        for (int it = 0; it < 2; it++) {
            ra[it]  = *(const float4*)(A  + (size_t)(aRow + fr[it]) * SEQ + k0 + fc[it]);
            rbv[it] = *(const float4*)(Bp + (size_t)(k0 + rb_[it]) * DIM + bx * BN + cb_[it]);
        }

#pragma unroll
        for (int kk = 0; kk < BK; kk++) {
            float a[TM], bfr[TN];
            *(float4*)&a[0]   = *(const float4*)&As[buf][kk][row0];
            *(float4*)&a[4]   = *(const float4*)&As[buf][kk][row0 + 4];
            *(float4*)&bfr[0] = *(const float4*)&Bs[buf][kk][col0];
            *(float4*)&bfr[4] = *(const float4*)&Bs[buf][kk][col0 + 4];
#pragma unroll
            for (int i = 0; i < TM; i++)
#pragma unroll
                for (int j = 0; j < TN; j++) acc[i][j] += a[i] * bfr[j];
        }

        const int nb = buf ^ 1;
#pragma unroll
        for (int it = 0; it < 2; it++) {
            As[nb][fc[it] + 0][fr[it]] = ra[it].x; As[nb][fc[it] + 1][fr[it]] = ra[it].y;
            As[nb][fc[it] + 2][fr[it]] = ra[it].z; As[nb][fc[it] + 3][fr[it]] = ra[it].w;
            *(float4*)&Bs[nb][rb_[it]][cb_[it]] = rbv[it];
        }
        __syncthreads();
        buf = nb;
    }

#pragma unroll
    for (int kk = 0; kk < BK; kk++) {
        float a[TM], bfr[TN];
        *(float4*)&a[0]   = *(const float4*)&As[buf][kk][row0];
        *(float4*)&a[4]   = *(const float4*)&As[buf][kk][row0 + 4];
        *(float4*)&bfr[0] = *(const float4*)&Bs[buf][kk][col0];
        *(float4*)&bfr[4] = *(const float4*)&Bs[buf][kk][col0 + 4];
#pragma unroll
        for (int i = 0; i < TM; i++)
#pragma unroll
            for (int j = 0; j < TN; j++) acc[i][j] += a[i] * bfr[j];
    }

#pragma unroll
    for (int i = 0; i < TM; i++) {
        float* cp = C + (size_t)(aRow + row0 + i) * DIM + bx * BN + col0;
        *(float4*)(cp)     = make_float4(acc[i][0], acc[i][1], acc[i][2], acc[i][3]);
        *(float4*)(cp + 4) = make_float4(acc[i][4], acc[i][5], acc[i][6], acc[i][7]);
    }
}

// ---------------------------------------------------------------------------
// Launch
// ---------------------------------------------------------------------------
extern "C" void kernel_launch(void* const* d_in, const int* in_sizes, int n_in,
                              void* d_out, int out_size)
{
    const float* x  = (const float*)d_in[0];   // [B, SEQ, DIM]
    const float* Wq = (const float*)d_in[1];   // [DIM, DIM]
    const float* Wk = (const float*)d_in[2];
    const float* Wv = (const float*)d_in[3];
    float* out = (float*)d_out;                // [B, SEQ, DIM]

    dim3 gridQKV(DIM / BN, (BATCH * SEQ) / BM, 3);
    qkv_gemm_kernel<<<gridQKV, NTHREADS>>>(x, Wq, Wk, Wv);

    dim3 gridS(SEQ / BN, SEQ / BM, BATCH);
    scores_gemm_kernel<<<gridS, NTHREADS>>>();

    softmax_kernel<<<BATCH * SEQ, NTHREADS>>>();

    dim3 gridPV(DIM / BN, SEQ / BM, BATCH);
    pv_gemm_kernel<<<gridPV, NTHREADS>>>(out);
}

// round 4
// speedup vs baseline: 1.9162x; 1.9162x over previous
#include <cuda_runtime.h>
#include <cuda_bf16.h>
#include <stdint.h>
#include <math.h>

// ---------------------------------------------------------------------------
// Problem constants
// ---------------------------------------------------------------------------
#define BATCH 4
#define SEQ   2048
#define DIM   1024
#define ROWS_TOT (BATCH * SEQ)   // 8192

// CTA tile 128x128, K stage 32. 8 warps, warp tile 64x32 (4 m-tiles x 4 n-tiles
// of m16n8k16).
#define BK 32
#define ASTR  80            // smem row stride bytes for [128 x 32] bf16 tile (+16 pad)
#define ATILE (128 * ASTR)  // 10240 B
#define BSTR1 272           // smem row stride for V tile [32 x 128] bf16 (+16 pad)
#define BTILE1 (32 * BSTR1) // 8704 B
#define STG_NT (2 * ATILE + 2 * ATILE)    // Ahi,Alo,Bhi,Blo (K-major B) = 40960
#define STG_NN (2 * ATILE + 2 * BTILE1)   // Phi,Plo,Vhi,Vlo            = 37888
#define SMEM_NT (2 * STG_NT)  // 81920
#define SMEM_NN (2 * STG_NN)  // 75776

// ---------------------------------------------------------------------------
// Device scratch (static globals — allocation-free)
// ---------------------------------------------------------------------------
__device__ __nv_bfloat16 g_xs_hi[(size_t)ROWS_TOT * DIM];
__device__ __nv_bfloat16 g_xs_lo[(size_t)ROWS_TOT * DIM];
__device__ __nv_bfloat16 g_w_hi[3ull * DIM * DIM];
__device__ __nv_bfloat16 g_w_lo[3ull * DIM * DIM];
__device__ __nv_bfloat16 g_q_hi[(size_t)ROWS_TOT * DIM];
__device__ __nv_bfloat16 g_q_lo[(size_t)ROWS_TOT * DIM];
__device__ __nv_bfloat16 g_k_hi[(size_t)ROWS_TOT * DIM];
__device__ __nv_bfloat16 g_k_lo[(size_t)ROWS_TOT * DIM];
__device__ __nv_bfloat16 g_v_hi[(size_t)ROWS_TOT * DIM];
__device__ __nv_bfloat16 g_v_lo[(size_t)ROWS_TOT * DIM];
__device__ float         g_s   [(size_t)BATCH * SEQ * SEQ];
__device__ __nv_bfloat16 g_p_hi[(size_t)BATCH * SEQ * SEQ];
__device__ __nv_bfloat16 g_p_lo[(size_t)BATCH * SEQ * SEQ];

// ---------------------------------------------------------------------------
// PTX helpers (all baseline ISA, valid at .target sm_100)
// ---------------------------------------------------------------------------
__device__ __forceinline__ uint32_t smem_u32(const void* p) {
    uint32_t a;
    asm("{ .reg .u64 t; cvta.to.shared.u64 t, %1; cvt.u32.u64 %0, t; }"
        : "=r"(a) : "l"(p));
    return a;
}

#define CP_ASYNC16(sm, g) \
    asm volatile("cp.async.cg.shared.global [%0], [%1], 16;" \
                 :: "r"(sm), "l"(g) : "memory")
#define CP_COMMIT() asm volatile("cp.async.commit_group;" ::: "memory")

__device__ __forceinline__ void ldm4(uint32_t* r, uint32_t addr) {
    asm volatile("ldmatrix.sync.aligned.m8n8.x4.shared.b16 {%0,%1,%2,%3}, [%4];"
                 : "=r"(r[0]), "=r"(r[1]), "=r"(r[2]), "=r"(r[3]) : "r"(addr));
}
__device__ __forceinline__ void ldm4t(uint32_t* r, uint32_t addr) {
    asm volatile("ldmatrix.sync.aligned.m8n8.x4.trans.shared.b16 {%0,%1,%2,%3}, [%4];"
                 : "=r"(r[0]), "=r"(r[1]), "=r"(r[2]), "=r"(r[3]) : "r"(addr));
}
__device__ __forceinline__ void mma_bf16(float* d, const uint32_t* a,
                                         const uint32_t* b) {
    asm volatile(
        "mma.sync.aligned.m16n8k16.row.col.f32.bf16.bf16.f32 "
        "{%0,%1,%2,%3}, {%4,%5,%6,%7}, {%8,%9}, {%0,%1,%2,%3};"
        : "+f"(d[0]), "+f"(d[1]), "+f"(d[2]), "+f"(d[3])
        : "r"(a[0]), "r"(a[1]), "r"(a[2]), "r"(a[3]), "r"(b[0]), "r"(b[1]));
}

// ---------------------------------------------------------------------------
// Core GEMM: C(128x128) = alpha * (Ahi+Alo) @ (Bhi+Blo)^T   (3-pass bf16 split)
// BL=0: B is [n][k] row-major (K-major operand, NT)   — QKV, scores
// BL=1: B is [k][n] row-major (V natural layout, NN)  — PV (ldmatrix.trans)
// MODE=0: write fp32*alpha to Cf.  MODE=1: write hi/lo bf16 split to Chi/Clo.
// Pointers are pre-offset to the CTA tile origin (k=0).
// ---------------------------------------------------------------------------
template<int MODE, int BL>
__device__ __forceinline__ void mma_core(
    const __nv_bfloat16* __restrict__ Ahi, const __nv_bfloat16* __restrict__ Alo,
    int lda,
    const __nv_bfloat16* __restrict__ Bhi, const __nv_bfloat16* __restrict__ Blo,
    int ldb,
    int nk, float alpha,
    float* __restrict__ Cf, __nv_bfloat16* __restrict__ Chi,
    __nv_bfloat16* __restrict__ Clo, int ldc)
{
    extern __shared__ char smem[];
    const uint32_t sbase = smem_u32(smem);
    const int tid = threadIdx.x, lane = tid & 31, wid = tid >> 5;
    const int wm = (wid & 1) * 64;     // warp row offset (2 warps over M)
    const int wn = (wid >> 1) * 32;    // warp col offset (4 warps over N)

    const int BTILE = BL ? BTILE1 : ATILE;
    const int STG   = 2 * ATILE + 2 * BTILE;

    // cp.async per-thread coords (2 x 16B per tile per thread)
    auto load_stage = [&](int s, int buf) {
        const size_t k0 = (size_t)s * BK;
        const uint32_t sb = sbase + buf * STG;
#pragma unroll
        for (int i = 0; i < 2; i++) {
            int f = tid + i * 256;              // 0..511
            int r = f >> 2, c = f & 3;          // A/P tile: 128 rows x 4 chunks
            size_t go = ((size_t)r * lda + k0 + c * 8) * 2;
            uint32_t so = r * ASTR + c * 16;
            CP_ASYNC16(sb + so,          (const char*)Ahi + go);
            CP_ASYNC16(sb + ATILE + so,  (const char*)Alo + go);
        }
        if (BL == 0) {
#pragma unroll
            for (int i = 0; i < 2; i++) {
                int f = tid + i * 256;
                int r = f >> 2, c = f & 3;
                size_t go = ((size_t)r * ldb + k0 + c * 8) * 2;
                uint32_t so = r * ASTR + c * 16;
                CP_ASYNC16(sb + 2 * ATILE + so,         (const char*)Bhi + go);
                CP_ASYNC16(sb + 2 * ATILE + BTILE + so, (const char*)Blo + go);
            }
        } else {
#pragma unroll
            for (int i = 0; i < 2; i++) {
                int f = tid + i * 256;
                int r = f >> 4, c = f & 15;     // V tile: 32 rows x 16 chunks
                size_t go = ((size_t)(k0 + r) * ldb + c * 8) * 2;
                uint32_t so = r * BSTR1 + c * 16;
                CP_ASYNC16(sb + 2 * ATILE + so,         (const char*)Bhi + go);
                CP_ASYNC16(sb + 2 * ATILE + BTILE + so, (const char*)Blo + go);
            }
        }
        CP_COMMIT();
    };

    float acc[4][4][4];
#pragma unroll
    for (int i = 0; i < 4; i++)
#pragma unroll
        for (int j = 0; j < 4; j++)
#pragma unroll
            for (int t = 0; t < 4; t++) acc[i][j][t] = 0.0f;

    // ldmatrix per-lane address pieces
    const int arow = (lane & 7) + ((lane >> 3) & 1) * 8;       // A groups
    const int asel = ((lane >> 4) & 1) * 16;                   // k halves (bytes)
    const int brow0 = (lane & 7) + ((lane >> 4) & 1) * 8;      // B NT groups
    const int bsel0 = ((lane >> 3) & 1) * 16;
    const int brow1 = (lane & 7) + ((lane >> 3) & 1) * 8;      // B NN (trans)
    const int bsel1 = ((lane >> 4) & 1) * 8;

    load_stage(0, 0);
    int buf = 0;
    for (int s = 0; s < nk; s++) {
        if (s + 1 < nk) {
            load_stage(s + 1, buf ^ 1);
            asm volatile("cp.async.wait_group 1;" ::: "memory");
        } else {
            asm volatile("cp.async.wait_group 0;" ::: "memory");
        }
        __syncthreads();

        const uint32_t sb = sbase + buf * STG;
#pragma unroll
        for (int kk = 0; kk < BK; kk += 16) {
            uint32_t ahi[4][4], alo[4][4];
#pragma unroll
            for (int mt = 0; mt < 4; mt++) {
                uint32_t ad = sb + (wm + mt * 16 + arow) * ASTR + kk * 2 + asel;
                ldm4(ahi[mt], ad);
                ldm4(alo[mt], ad + ATILE);
            }
#pragma unroll
            for (int np = 0; np < 2; np++) {
                uint32_t bh[4], bl[4];
                if (BL == 0) {
                    uint32_t bd = sb + 2 * ATILE
                                + (wn + np * 16 + brow0) * ASTR + kk * 2 + bsel0;
                    ldm4(bh, bd); ldm4(bl, bd + BTILE);
                } else {
                    uint32_t bd = sb + 2 * ATILE + (kk + brow1) * BSTR1
                                + (wn + np * 16 + bsel1) * 2;
                    ldm4t(bh, bd); ldm4t(bl, bd + BTILE);
                }
#pragma unroll
                for (int mt = 0; mt < 4; mt++) {
                    mma_bf16(acc[mt][np * 2],     ahi[mt], bh);      // hi*hi
                    mma_bf16(acc[mt][np * 2 + 1], ahi[mt], bh + 2);
                    mma_bf16(acc[mt][np * 2],     ahi[mt], bl);      // hi*lo
                    mma_bf16(acc[mt][np * 2 + 1], ahi[mt], bl + 2);
                    mma_bf16(acc[mt][np * 2],     alo[mt], bh);      // lo*hi
                    mma_bf16(acc[mt][np * 2 + 1], alo[mt], bh + 2);
                }
            }
        }
        __syncthreads();
        buf ^= 1;
    }

    // Epilogue: c0,c1 -> row m, cols n..n+1; c2,c3 -> row m+8
    const int er = lane >> 2, ec = (lane & 3) * 2;
#pragma unroll
    for (int mt = 0; mt < 4; mt++) {
#pragma unroll
        for (int nt = 0; nt < 4; nt++) {
            const float* c = acc[mt][nt];
            const int m = wm + mt * 16 + er;
            const int n = wn + nt * 8 + ec;
            if (MODE == 0) {
                size_t o = (size_t)m * ldc + n;
                Cf[o]     = c[0] * alpha;  Cf[o + 1] = c[1] * alpha;
                o += (size_t)8 * ldc;
                Cf[o]     = c[2] * alpha;  Cf[o + 1] = c[3] * alpha;
            } else {
#pragma unroll
                for (int h = 0; h < 2; h++) {
                    size_t o = (size_t)(m + h * 8) * ldc + n;
#pragma unroll
                    for (int j = 0; j < 2; j++) {
                        float v = c[h * 2 + j];
                        __nv_bfloat16 hi = __float2bfloat16(v);
                        Chi[o + j] = hi;
                        Clo[o + j] = __float2bfloat16(v - __bfloat162float(hi));
                    }
                }
            }
        }
    }
}

// ---------------------------------------------------------------------------
// Kernels
// ---------------------------------------------------------------------------
__global__ void __launch_bounds__(256, 1)
split_kernel(const float* __restrict__ src, int which)   // fp32 -> hi/lo bf16
{
    __nv_bfloat16 *hi, *lo;
    int n;
    if (which == 0) { hi = g_xs_hi; lo = g_xs_lo; n = ROWS_TOT * DIM; }
    else {
        size_t off = (size_t)(which - 1) * DIM * DIM;
        hi = g_w_hi + off; lo = g_w_lo + off; n = DIM * DIM;
    }
    int i = blockIdx.x * 256 + threadIdx.x;
    if (i < n) {
        float v = src[i];
        __nv_bfloat16 h = __float2bfloat16(v);
        hi[i] = h;
        lo[i] = __float2bfloat16(v - __bfloat162float(h));
    }
}

__global__ void __launch_bounds__(256, 1)
qkv_kernel()   // {Q,K,V} = X @ W^T; outputs hi/lo bf16
{
    const int bx = blockIdx.x, by = blockIdx.y, z = blockIdx.z;
    const size_t ao = (size_t)by * 128 * DIM;
    const size_t wo = (size_t)z * DIM * DIM + (size_t)bx * 128 * DIM;
    __nv_bfloat16* Chi = (z == 0 ? g_q_hi : z == 1 ? g_k_hi : g_v_hi)
                         + (size_t)by * 128 * DIM + (size_t)bx * 128;
    __nv_bfloat16* Clo = (z == 0 ? g_q_lo : z == 1 ? g_k_lo : g_v_lo)
                         + (size_t)by * 128 * DIM + (size_t)bx * 128;
    mma_core<1, 0>(g_xs_hi + ao, g_xs_lo + ao, DIM,
                   g_w_hi + wo, g_w_lo + wo, DIM,
                   DIM / BK, 1.0f, nullptr, Chi, Clo, DIM);
}

__global__ void __launch_bounds__(256, 1)
scores_kernel()   // S = (1/32) Q K^T, masked blocks skipped, fp32 out
{
    const int bx = blockIdx.x, by = blockIdx.y, b = blockIdx.z;
    if (bx > by) return;
    const size_t ao = ((size_t)b * SEQ + (size_t)by * 128) * DIM;
    const size_t bo = ((size_t)b * SEQ + (size_t)bx * 128) * DIM;
    float* Cf = g_s + (size_t)b * SEQ * SEQ + (size_t)by * 128 * SEQ
                    + (size_t)bx * 128;
    mma_core<0, 0>(g_q_hi + ao, g_q_lo + ao, DIM,
                   g_k_hi + bo, g_k_lo + bo, DIM,
                   DIM / BK, 0.03125f, Cf, nullptr, nullptr, SEQ);
}

__global__ void __launch_bounds__(256)
softmax_kernel()   // causal row softmax; emit P as hi/lo bf16, zero-filled
{
    const int row = blockIdx.x;               // 0..8191
    const int i   = row & (SEQ - 1);
    const size_t ro = (size_t)row * SEQ;
    const float* s = g_s + ro;
    const int len = i + 1, tid = threadIdx.x;

    __shared__ float red[256];

    float m = -1e30f;
    for (int j = tid; j < len; j += 256) m = fmaxf(m, s[j]);
    red[tid] = m; __syncthreads();
    for (int st = 128; st > 0; st >>= 1) {
        if (tid < st) red[tid] = fmaxf(red[tid], red[tid + st]);
        __syncthreads();
    }
    m = red[0]; __syncthreads();

    float sum = 0.0f;
    for (int j = tid; j < len; j += 256) sum += expf(s[j] - m);
    red[tid] = sum; __syncthreads();
    for (int st = 128; st > 0; st >>= 1) {
        if (tid < st) red[tid] += red[tid + st];
        __syncthreads();
    }
    const float inv = 1.0f / red[0];

    const int lenPad = ((i >> 7) + 1) << 7;   // causal block boundary
    for (int j = tid; j < lenPad; j += 256) {
        float p = (j < len) ? expf(s[j] - m) * inv : 0.0f;
        __nv_bfloat16 h = __float2bfloat16(p);
        g_p_hi[ro + j] = h;
        g_p_lo[ro + j] = __float2bfloat16(p - __bfloat162float(h));
    }
}

__global__ void __launch_bounds__(256, 1)
pv_kernel(float* __restrict__ out)   // O = P @ V, causal-truncated K loop
{
    const int bx = blockIdx.x, by = blockIdx.y, b = blockIdx.z;
    const size_t ao = ((size_t)b * SEQ + (size_t)by * 128) * SEQ;
    const size_t vo = (size_t)b * SEQ * DIM + (size_t)bx * 128;
    float* Cf = out + ((size_t)b * SEQ + (size_t)by * 128) * DIM
                    + (size_t)bx * 128;
    mma_core<0, 1>(g_p_hi + ao, g_p_lo + ao, SEQ,
                   g_v_hi + vo, g_v_lo + vo, DIM,
                   (by + 1) * (128 / BK), 1.0f, Cf, nullptr, nullptr, DIM);
}

// ---------------------------------------------------------------------------
// Launch
// ---------------------------------------------------------------------------
extern "C" void kernel_launch(void* const* d_in, const int* in_sizes, int n_in,
                              void* d_out, int out_size)
{
    const float* x  = (const float*)d_in[0];
    const float* Wq = (const float*)d_in[1];
    const float* Wk = (const float*)d_in[2];
    const float* Wv = (const float*)d_in[3];
    float* out = (float*)d_out;

    cudaFuncSetAttribute(qkv_kernel,
        cudaFuncAttributeMaxDynamicSharedMemorySize, SMEM_NT);
    cudaFuncSetAttribute(scores_kernel,
        cudaFuncAttributeMaxDynamicSharedMemorySize, SMEM_NT);
    cudaFuncSetAttribute(pv_kernel,
        cudaFuncAttributeMaxDynamicSharedMemorySize, SMEM_NN);

    split_kernel<<<(ROWS_TOT * DIM) / 256, 256>>>(x, 0);
    split_kernel<<<(DIM * DIM) / 256, 256>>>(Wq, 1);
    split_kernel<<<(DIM * DIM) / 256, 256>>>(Wk, 2);
    split_kernel<<<(DIM * DIM) / 256, 256>>>(Wv, 3);

    dim3 gq(DIM / 128, ROWS_TOT / 128, 3);
    qkv_kernel<<<gq, 256, SMEM_NT>>>();

    dim3 gs(SEQ / 128, SEQ / 128, BATCH);
    scores_kernel<<<gs, 256, SMEM_NT>>>();

    softmax_kernel<<<BATCH * SEQ, 256>>>();

    dim3 gp(DIM / 128, SEQ / 128, BATCH);
    pv_kernel<<<gp, 256, SMEM_NN>>>(out);
}

// round 5
// speedup vs baseline: 2.0949x; 1.0933x over previous
#include <cuda_runtime.h>
#include <cuda_bf16.h>
#include <stdint.h>
#include <math.h>

// ---------------------------------------------------------------------------
// Problem constants
// ---------------------------------------------------------------------------
#define BATCH 4
#define SEQ   2048
#define DIM   1024
#define ROWS_TOT (BATCH * SEQ)   // 8192

// CTA tile 128x128, K stage 32, 3-stage cp.async pipeline.
// 8 warps, warp tile 64x32 (4 m-tiles x 4 n-tiles of m16n8k16).
#define BK 32
#define ASTR  80            // smem row stride bytes, [128 x 32] bf16 tile (+16 pad)
#define ATILE (128 * ASTR)  // 10240 B
#define BSTR1 272           // smem row stride, V tile [32 x 128] bf16 (+16 pad)
#define BTILE1 (32 * BSTR1) // 8704 B
#define STG_NT (2 * ATILE + 2 * ATILE)    // Ahi,Alo,Bhi,Blo = 40960
#define STG_NN (2 * ATILE + 2 * BTILE1)   // Phi,Plo,Vhi,Vlo = 37888
#define SMEM_NT (3 * STG_NT)  // 122880
#define SMEM_NN (3 * STG_NN)  // 113664

// ---------------------------------------------------------------------------
// Device scratch (static globals — allocation-free)
// ---------------------------------------------------------------------------
__device__ __nv_bfloat16 g_xs_hi[(size_t)ROWS_TOT * DIM];
__device__ __nv_bfloat16 g_xs_lo[(size_t)ROWS_TOT * DIM];
__device__ __nv_bfloat16 g_w_hi[3ull * DIM * DIM];
__device__ __nv_bfloat16 g_w_lo[3ull * DIM * DIM];
__device__ __nv_bfloat16 g_q_hi[(size_t)ROWS_TOT * DIM];
__device__ __nv_bfloat16 g_q_lo[(size_t)ROWS_TOT * DIM];
__device__ __nv_bfloat16 g_k_hi[(size_t)ROWS_TOT * DIM];
__device__ __nv_bfloat16 g_k_lo[(size_t)ROWS_TOT * DIM];
__device__ __nv_bfloat16 g_v_hi[(size_t)ROWS_TOT * DIM];
__device__ __nv_bfloat16 g_v_lo[(size_t)ROWS_TOT * DIM];
__device__ float         g_s   [(size_t)BATCH * SEQ * SEQ];
__device__ __nv_bfloat16 g_p_hi[(size_t)BATCH * SEQ * SEQ];
__device__ __nv_bfloat16 g_p_lo[(size_t)BATCH * SEQ * SEQ];

// ---------------------------------------------------------------------------
// PTX helpers (baseline ISA, valid at .target sm_100)
// ---------------------------------------------------------------------------
__device__ __forceinline__ uint32_t smem_u32(const void* p) {
    uint32_t a;
    asm("{ .reg .u64 t; cvta.to.shared.u64 t, %1; cvt.u32.u64 %0, t; }"
        : "=r"(a) : "l"(p));
    return a;
}

#define CP_ASYNC16(sm, g) \
    asm volatile("cp.async.cg.shared.global [%0], [%1], 16;" \
                 :: "r"(sm), "l"(g) : "memory")
#define CP_COMMIT() asm volatile("cp.async.commit_group;" ::: "memory")

__device__ __forceinline__ void ldm4(uint32_t* r, uint32_t addr) {
    asm volatile("ldmatrix.sync.aligned.m8n8.x4.shared.b16 {%0,%1,%2,%3}, [%4];"
                 : "=r"(r[0]), "=r"(r[1]), "=r"(r[2]), "=r"(r[3]) : "r"(addr));
}
__device__ __forceinline__ void ldm4t(uint32_t* r, uint32_t addr) {
    asm volatile("ldmatrix.sync.aligned.m8n8.x4.trans.shared.b16 {%0,%1,%2,%3}, [%4];"
                 : "=r"(r[0]), "=r"(r[1]), "=r"(r[2]), "=r"(r[3]) : "r"(addr));
}
__device__ __forceinline__ void mma_bf16(float* d, const uint32_t* a,
                                         const uint32_t* b) {
    asm volatile(
        "mma.sync.aligned.m16n8k16.row.col.f32.bf16.bf16.f32 "
        "{%0,%1,%2,%3}, {%4,%5,%6,%7}, {%8,%9}, {%0,%1,%2,%3};"
        : "+f"(d[0]), "+f"(d[1]), "+f"(d[2]), "+f"(d[3])
        : "r"(a[0]), "r"(a[1]), "r"(a[2]), "r"(a[3]), "r"(b[0]), "r"(b[1]));
}

__device__ __forceinline__ uint32_t pack_bf16x2(float a, float b) {
    __nv_bfloat162 h = __floats2bfloat162_rn(a, b);
    return *(uint32_t*)&h;
}

// ---------------------------------------------------------------------------
// Core GEMM: C(128x128) = alpha * (Ahi+Alo) @ (Bhi+Blo)^T   (3-pass bf16 split)
// BL=0: B is [n][k] row-major (K-major, NT)  — QKV, scores
// BL=1: B is [k][n] row-major (V layout, NN) — PV (ldmatrix.trans)
// MODE=0: write fp32*alpha to Cf.  MODE=1: write hi/lo bf16 split to Chi/Clo.
// ---------------------------------------------------------------------------
template<int MODE, int BL>
__device__ __forceinline__ void mma_core(
    const __nv_bfloat16* __restrict__ Ahi, const __nv_bfloat16* __restrict__ Alo,
    int lda,
    const __nv_bfloat16* __restrict__ Bhi, const __nv_bfloat16* __restrict__ Blo,
    int ldb,
    int nk, float alpha,
    float* __restrict__ Cf, __nv_bfloat16* __restrict__ Chi,
    __nv_bfloat16* __restrict__ Clo, int ldc)
{
    extern __shared__ char smem[];
    const uint32_t sbase = smem_u32(smem);
    const int tid = threadIdx.x, lane = tid & 31, wid = tid >> 5;
    const int wm = (wid & 1) * 64;     // warp row offset (2 warps over M)
    const int wn = (wid >> 1) * 32;    // warp col offset (4 warps over N)

    const int BTILE = BL ? BTILE1 : ATILE;
    const int STG   = 2 * ATILE + 2 * BTILE;

    auto load_stage = [&](int s, int buf) {
        const size_t k0 = (size_t)s * BK;
        const uint32_t sb = sbase + buf * STG;
#pragma unroll
        for (int i = 0; i < 2; i++) {
            int f = tid + i * 256;              // 0..511
            int r = f >> 2, c = f & 3;          // A/P tile: 128 rows x 4 chunks
            size_t go = ((size_t)r * lda + k0 + c * 8) * 2;
            uint32_t so = r * ASTR + c * 16;
            CP_ASYNC16(sb + so,          (const char*)Ahi + go);
            CP_ASYNC16(sb + ATILE + so,  (const char*)Alo + go);
        }
        if (BL == 0) {
#pragma unroll
            for (int i = 0; i < 2; i++) {
                int f = tid + i * 256;
                int r = f >> 2, c = f & 3;
                size_t go = ((size_t)r * ldb + k0 + c * 8) * 2;
                uint32_t so = r * ASTR + c * 16;
                CP_ASYNC16(sb + 2 * ATILE + so,         (const char*)Bhi + go);
                CP_ASYNC16(sb + 2 * ATILE + BTILE + so, (const char*)Blo + go);
            }
        } else {
#pragma unroll
            for (int i = 0; i < 2; i++) {
                int f = tid + i * 256;
                int r = f >> 4, c = f & 15;     // V tile: 32 rows x 16 chunks
                size_t go = ((size_t)(k0 + r) * ldb + c * 8) * 2;
                uint32_t so = r * BSTR1 + c * 16;
                CP_ASYNC16(sb + 2 * ATILE + so,         (const char*)Bhi + go);
                CP_ASYNC16(sb + 2 * ATILE + BTILE + so, (const char*)Blo + go);
            }
        }
        CP_COMMIT();
    };

    float acc[4][4][4];
#pragma unroll
    for (int i = 0; i < 4; i++)
#pragma unroll
        for (int j = 0; j < 4; j++)
#pragma unroll
            for (int t = 0; t < 4; t++) acc[i][j][t] = 0.0f;

    // ldmatrix per-lane address pieces
    const int arow = (lane & 7) + ((lane >> 3) & 1) * 8;       // A groups
    const int asel = ((lane >> 4) & 1) * 16;                   // k halves (bytes)
    const int brow0 = (lane & 7) + ((lane >> 4) & 1) * 8;      // B NT groups
    const int bsel0 = ((lane >> 3) & 1) * 16;
    const int brow1 = (lane & 7) + ((lane >> 3) & 1) * 8;      // B NN (trans)
    const int bsel1 = ((lane >> 4) & 1) * 8;

    // 3-stage prologue: stages 0,1 in flight
    load_stage(0, 0);
    if (nk > 1) load_stage(1, 1);

    for (int s = 0; s < nk; s++) {
        if (s + 2 < nk) load_stage(s + 2, (s + 2) % 3);
        // wait until stage s complete: allow `ahead` groups still pending
        const int ahead = (nk - 1 - s > 2) ? 2 : (nk - 1 - s);
        if (ahead == 2)      asm volatile("cp.async.wait_group 2;" ::: "memory");
        else if (ahead == 1) asm volatile("cp.async.wait_group 1;" ::: "memory");
        else                 asm volatile("cp.async.wait_group 0;" ::: "memory");
        __syncthreads();

        const uint32_t sb = sbase + (s % 3) * STG;
#pragma unroll
        for (int kk = 0; kk < BK; kk += 16) {
            uint32_t ahi[4][4], alo[4][4];
#pragma unroll
            for (int mt = 0; mt < 4; mt++) {
                uint32_t ad = sb + (wm + mt * 16 + arow) * ASTR + kk * 2 + asel;
                ldm4(ahi[mt], ad);
                ldm4(alo[mt], ad + ATILE);
            }
#pragma unroll
            for (int np = 0; np < 2; np++) {
                uint32_t bh[4], bl[4];
                if (BL == 0) {
                    uint32_t bd = sb + 2 * ATILE
                                + (wn + np * 16 + brow0) * ASTR + kk * 2 + bsel0;
                    ldm4(bh, bd); ldm4(bl, bd + BTILE);
                } else {
                    uint32_t bd = sb + 2 * ATILE + (kk + brow1) * BSTR1
                                + (wn + np * 16 + bsel1) * 2;
                    ldm4t(bh, bd); ldm4t(bl, bd + BTILE);
                }
                // Pass-grouped issue: dependency distance 8 on each acc pair
#pragma unroll
                for (int mt = 0; mt < 4; mt++) {          // hi * hi
                    mma_bf16(acc[mt][np * 2],     ahi[mt], bh);
                    mma_bf16(acc[mt][np * 2 + 1], ahi[mt], bh + 2);
                }
#pragma unroll
                for (int mt = 0; mt < 4; mt++) {          // hi * lo
                    mma_bf16(acc[mt][np * 2],     ahi[mt], bl);
                    mma_bf16(acc[mt][np * 2 + 1], ahi[mt], bl + 2);
                }
#pragma unroll
                for (int mt = 0; mt < 4; mt++) {          // lo * hi
                    mma_bf16(acc[mt][np * 2],     alo[mt], bh);
                    mma_bf16(acc[mt][np * 2 + 1], alo[mt], bh + 2);
                }
            }
        }
        __syncthreads();
    }

    // Epilogue: c0,c1 -> row m cols n..n+1; c2,c3 -> row m+8. Packed stores.
    const int er = lane >> 2, ec = (lane & 3) * 2;
#pragma unroll
    for (int mt = 0; mt < 4; mt++) {
#pragma unroll
        for (int nt = 0; nt < 4; nt++) {
            const float* c = acc[mt][nt];
            const int m = wm + mt * 16 + er;
            const int n = wn + nt * 8 + ec;
            if (MODE == 0) {
                size_t o = (size_t)m * ldc + n;
                *(float2*)(Cf + o) = make_float2(c[0] * alpha, c[1] * alpha);
                o += (size_t)8 * ldc;
                *(float2*)(Cf + o) = make_float2(c[2] * alpha, c[3] * alpha);
            } else {
#pragma unroll
                for (int h = 0; h < 2; h++) {
                    size_t o = (size_t)(m + h * 8) * ldc + n;
                    float v0 = c[h * 2], v1 = c[h * 2 + 1];
                    __nv_bfloat16 h0 = __float2bfloat16(v0);
                    __nv_bfloat16 h1 = __float2bfloat16(v1);
                    *(uint32_t*)(Chi + o) = pack_bf16x2(v0, v1);
                    *(uint32_t*)(Clo + o) =
                        pack_bf16x2(v0 - __bfloat162float(h0),
                                    v1 - __bfloat162float(h1));
                }
            }
        }
    }
}

// ---------------------------------------------------------------------------
// Kernels
// ---------------------------------------------------------------------------
__global__ void __launch_bounds__(256, 1)
split_kernel(const float* __restrict__ src, int which)   // fp32 -> hi/lo, x4
{
    __nv_bfloat16 *hi, *lo;
    int n4;
    if (which == 0) { hi = g_xs_hi; lo = g_xs_lo; n4 = (ROWS_TOT * DIM) / 4; }
    else {
        size_t off = (size_t)(which - 1) * DIM * DIM;
        hi = g_w_hi + off; lo = g_w_lo + off; n4 = (DIM * DIM) / 4;
    }
    int i = blockIdx.x * 256 + threadIdx.x;
    if (i < n4) {
        float4 v = ((const float4*)src)[i];
        __nv_bfloat16 h0 = __float2bfloat16(v.x), h1 = __float2bfloat16(v.y);
        __nv_bfloat16 h2 = __float2bfloat16(v.z), h3 = __float2bfloat16(v.w);
        uint2 ph, pl;
        ph.x = pack_bf16x2(v.x, v.y);
        ph.y = pack_bf16x2(v.z, v.w);
        pl.x = pack_bf16x2(v.x - __bfloat162float(h0),
                           v.y - __bfloat162float(h1));
        pl.y = pack_bf16x2(v.z - __bfloat162float(h2),
                           v.w - __bfloat162float(h3));
        ((uint2*)hi)[i] = ph;
        ((uint2*)lo)[i] = pl;
    }
}

__global__ void __launch_bounds__(256, 1)
qkv_kernel()   // {Q,K,V} = X @ W^T; outputs hi/lo bf16
{
    const int bx = blockIdx.x, by = blockIdx.y, z = blockIdx.z;
    const size_t ao = (size_t)by * 128 * DIM;
    const size_t wo = (size_t)z * DIM * DIM + (size_t)bx * 128 * DIM;
    __nv_bfloat16* Chi = (z == 0 ? g_q_hi : z == 1 ? g_k_hi : g_v_hi)
                         + (size_t)by * 128 * DIM + (size_t)bx * 128;
    __nv_bfloat16* Clo = (z == 0 ? g_q_lo : z == 1 ? g_k_lo : g_v_lo)
                         + (size_t)by * 128 * DIM + (size_t)bx * 128;
    mma_core<1, 0>(g_xs_hi + ao, g_xs_lo + ao, DIM,
                   g_w_hi + wo, g_w_lo + wo, DIM,
                   DIM / BK, 1.0f, nullptr, Chi, Clo, DIM);
}

__global__ void __launch_bounds__(256, 1)
scores_kernel()   // S = (1/32) Q K^T, masked blocks skipped, fp32 out
{
    const int bx = blockIdx.x, by = blockIdx.y, b = blockIdx.z;
    if (bx > by) return;
    const size_t ao = ((size_t)b * SEQ + (size_t)by * 128) * DIM;
    const size_t bo = ((size_t)b * SEQ + (size_t)bx * 128) * DIM;
    float* Cf = g_s + (size_t)b * SEQ * SEQ + (size_t)by * 128 * SEQ
                    + (size_t)bx * 128;
    mma_core<0, 0>(g_q_hi + ao, g_q_lo + ao, DIM,
                   g_k_hi + bo, g_k_lo + bo, DIM,
                   DIM / BK, 0.03125f, Cf, nullptr, nullptr, SEQ);
}

__global__ void __launch_bounds__(256)
softmax_kernel()   // causal row softmax; emit P hi/lo bf16, zero-filled; x4
{
    const int row = blockIdx.x;               // 0..8191
    const int i   = row & (SEQ - 1);
    const size_t ro = (size_t)row * SEQ;
    const float4* s4 = (const float4*)(g_s + ro);
    const int len = i + 1, tid = threadIdx.x;
    const int n4 = (((i >> 7) + 1) << 7) >> 2;   // lenPad / 4

    __shared__ float red[256];

    float m = -1e30f;
    for (int j4 = tid; j4 < n4; j4 += 256) {
        float4 v = s4[j4];
        int base = j4 * 4;
        v.x = (base + 0 < len) ? v.x : -1e30f;
        v.y = (base + 1 < len) ? v.y : -1e30f;
        v.z = (base + 2 < len) ? v.z : -1e30f;
        v.w = (base + 3 < len) ? v.w : -1e30f;
        m = fmaxf(m, fmaxf(fmaxf(v.x, v.y), fmaxf(v.z, v.w)));
    }
    red[tid] = m; __syncthreads();
    for (int st = 128; st > 0; st >>= 1) {
        if (tid < st) red[tid] = fmaxf(red[tid], red[tid + st]);
        __syncthreads();
    }
    m = red[0]; __syncthreads();

    float sum = 0.0f;
    for (int j4 = tid; j4 < n4; j4 += 256) {
        float4 v = s4[j4];
        int base = j4 * 4;
        sum += (base + 0 < len) ? __expf(v.x - m) : 0.0f;
        sum += (base + 1 < len) ? __expf(v.y - m) : 0.0f;
        sum += (base + 2 < len) ? __expf(v.z - m) : 0.0f;
        sum += (base + 3 < len) ? __expf(v.w - m) : 0.0f;
    }
    red[tid] = sum; __syncthreads();
    for (int st = 128; st > 0; st >>= 1) {
        if (tid < st) red[tid] += red[tid + st];
        __syncthreads();
    }
    const float inv = 1.0f / red[0];

    uint2* ph = (uint2*)(g_p_hi + ro);
    uint2* pl = (uint2*)(g_p_lo + ro);
    for (int j4 = tid; j4 < n4; j4 += 256) {
        float4 v = s4[j4];
        int base = j4 * 4;
        float p0 = (base + 0 < len) ? __expf(v.x - m) * inv : 0.0f;
        float p1 = (base + 1 < len) ? __expf(v.y - m) * inv : 0.0f;
        float p2 = (base + 2 < len) ? __expf(v.z - m) * inv : 0.0f;
        float p3 = (base + 3 < len) ? __expf(v.w - m) * inv : 0.0f;
        __nv_bfloat16 h0 = __float2bfloat16(p0), h1 = __float2bfloat16(p1);
        __nv_bfloat16 h2 = __float2bfloat16(p2), h3 = __float2bfloat16(p3);
        uint2 vh, vl;
        vh.x = pack_bf16x2(p0, p1);
        vh.y = pack_bf16x2(p2, p3);
        vl.x = pack_bf16x2(p0 - __bfloat162float(h0),
                           p1 - __bfloat162float(h1));
        vl.y = pack_bf16x2(p2 - __bfloat162float(h2),
                           p3 - __bfloat162float(h3));
        ph[j4] = vh;
        pl[j4] = vl;
    }
}

__global__ void __launch_bounds__(256, 1)
pv_kernel(float* __restrict__ out)   // O = P @ V, causal-truncated K loop
{
    const int bx = blockIdx.x, by = blockIdx.y, b = blockIdx.z;
    const size_t ao = ((size_t)b * SEQ + (size_t)by * 128) * SEQ;
    const size_t vo = (size_t)b * SEQ * DIM + (size_t)bx * 128;
    float* Cf = out + ((size_t)b * SEQ + (size_t)by * 128) * DIM
                    + (size_t)bx * 128;
    mma_core<0, 1>(g_p_hi + ao, g_p_lo + ao, SEQ,
                   g_v_hi + vo, g_v_lo + vo, DIM,
                   (by + 1) * (128 / BK), 1.0f, Cf, nullptr, nullptr, DIM);
}

// ---------------------------------------------------------------------------
// Launch
// ---------------------------------------------------------------------------
extern "C" void kernel_launch(void* const* d_in, const int* in_sizes, int n_in,
                              void* d_out, int out_size)
{
    const float* x  = (const float*)d_in[0];
    const float* Wq = (const float*)d_in[1];
    const float* Wk = (const float*)d_in[2];
    const float* Wv = (const float*)d_in[3];
    float* out = (float*)d_out;

    cudaFuncSetAttribute(qkv_kernel,
        cudaFuncAttributeMaxDynamicSharedMemorySize, SMEM_NT);
    cudaFuncSetAttribute(scores_kernel,
        cudaFuncAttributeMaxDynamicSharedMemorySize, SMEM_NT);
    cudaFuncSetAttribute(pv_kernel,
        cudaFuncAttributeMaxDynamicSharedMemorySize, SMEM_NN);

    split_kernel<<<(ROWS_TOT * DIM) / 1024, 256>>>(x, 0);
    split_kernel<<<(DIM * DIM) / 1024, 256>>>(Wq, 1);
    split_kernel<<<(DIM * DIM) / 1024, 256>>>(Wk, 2);
    split_kernel<<<(DIM * DIM) / 1024, 256>>>(Wv, 3);

    dim3 gq(DIM / 128, ROWS_TOT / 128, 3);
    qkv_kernel<<<gq, 256, SMEM_NT>>>();

    dim3 gs(SEQ / 128, SEQ / 128, BATCH);
    scores_kernel<<<gs, 256, SMEM_NT>>>();

    softmax_kernel<<<BATCH * SEQ, 256>>>();

    dim3 gp(DIM / 128, SEQ / 128, BATCH);
    pv_kernel<<<gp, 256, SMEM_NN>>>(out);
}

// round 7
// speedup vs baseline: 3.3499x; 1.5990x over previous
#include <cuda_runtime.h>
#include <stdint.h>
#include <math.h>

// ---------------------------------------------------------------------------
// Problem constants
// ---------------------------------------------------------------------------
#define BATCH 4
#define SEQ   2048
#define DIM   1024
#define ROWS_TOT (BATCH * SEQ)   // 8192

// GEMM: CTA tile 128x128, K stage = 64 int8 elems (64 bytes/row), 3-stage
// cp.async pipeline. 8 warps, warp tile 64x32 of m16n8k32 s8 MMAs.
#define BKB   64
#define ASTR  80             // smem row stride (64 data + 16 pad)
#define ATILE (128 * ASTR)   // 10240 B per tile
#define STG   (4 * ATILE)    // A1,A2,B1,B2 = 40960 B per stage
#define SMEM_SZ (3 * STG)    // 122880 B
#define INV254  (1.0f / 254.0f)

// ---------------------------------------------------------------------------
// Device scratch (static globals — allocation-free)
// ---------------------------------------------------------------------------
__device__ int8_t g_x1[(size_t)ROWS_TOT * DIM];
__device__ int8_t g_x2[(size_t)ROWS_TOT * DIM];
__device__ float  g_sx[ROWS_TOT];
__device__ int8_t g_w1[3ull * DIM * DIM];
__device__ int8_t g_w2[3ull * DIM * DIM];
__device__ float  g_sw[3 * DIM];
__device__ float  g_qf[(size_t)ROWS_TOT * DIM];
__device__ float  g_kf[(size_t)ROWS_TOT * DIM];
__device__ float  g_vf[(size_t)ROWS_TOT * DIM];
__device__ int8_t g_q1[(size_t)ROWS_TOT * DIM];
__device__ int8_t g_q2[(size_t)ROWS_TOT * DIM];
__device__ float  g_sq[ROWS_TOT];
__device__ int8_t g_k1[(size_t)ROWS_TOT * DIM];
__device__ int8_t g_k2[(size_t)ROWS_TOT * DIM];
__device__ float  g_sk[ROWS_TOT];
__device__ uint32_t g_svu[BATCH * DIM];          // |V| col-max as float bits
__device__ float  g_sv[BATCH * DIM];
__device__ int8_t g_vt1[(size_t)BATCH * DIM * SEQ];  // V^T digits [b][o][n]
__device__ int8_t g_vt2[(size_t)BATCH * DIM * SEQ];
__device__ float  g_s[(size_t)BATCH * SEQ * SEQ];
__device__ int8_t g_p1[(size_t)BATCH * SEQ * SEQ];
__device__ int8_t g_p2[(size_t)BATCH * SEQ * SEQ];
__device__ float  g_sp[ROWS_TOT];

// ---------------------------------------------------------------------------
// PTX helpers (baseline ISA, valid at .target sm_100)
// ---------------------------------------------------------------------------
__device__ __forceinline__ uint32_t smem_u32(const void* p) {
    uint32_t a;
    asm("{ .reg .u64 t; cvta.to.shared.u64 t, %1; cvt.u32.u64 %0, t; }"
        : "=r"(a) : "l"(p));
    return a;
}
#define CP_ASYNC16(sm, g) \
    asm volatile("cp.async.cg.shared.global [%0], [%1], 16;" \
                 :: "r"(sm), "l"(g) : "memory")
#define CP_COMMIT() asm volatile("cp.async.commit_group;" ::: "memory")

__device__ __forceinline__ void ldm4(uint32_t* r, uint32_t addr) {
    asm volatile("ldmatrix.sync.aligned.m8n8.x4.shared.b16 {%0,%1,%2,%3}, [%4];"
                 : "=r"(r[0]), "=r"(r[1]), "=r"(r[2]), "=r"(r[3]) : "r"(addr));
}
__device__ __forceinline__ void mma_s8(int* d, const uint32_t* a,
                                       const uint32_t* b) {
    asm volatile(
        "mma.sync.aligned.m16n8k32.row.col.s32.s8.s8.s32 "
        "{%0,%1,%2,%3}, {%4,%5,%6,%7}, {%8,%9}, {%0,%1,%2,%3};"
        : "+r"(d[0]), "+r"(d[1]), "+r"(d[2]), "+r"(d[3])
        : "r"(a[0]), "r"(a[1]), "r"(a[2]), "r"(a[3]), "r"(b[0]), "r"(b[1]));
}
__device__ __forceinline__ void quant2(float v, float inv, int8_t& d1, int8_t& d2) {
    float t  = v * inv;
    int   q1 = __float2int_rn(t);
    int   q2 = __float2int_rn((t - (float)q1) * 254.0f);
    d1 = (int8_t)q1; d2 = (int8_t)q2;
}

// ---------------------------------------------------------------------------
// Core int8 GEMM: C(128x128) = alpha*sA[m]*sB[n]*(Σd1a·d1b + Σcross/254)
// A digits: [128 x K] row-major; B digits: [128 x K] row-major (NT form).
// All pointers pre-offset to tile origin. nk = K/64 stages.
// ---------------------------------------------------------------------------
__device__ __forceinline__ void imma_core(
    const int8_t* __restrict__ A1, const int8_t* __restrict__ A2, int lda,
    const int8_t* __restrict__ B1, const int8_t* __restrict__ B2, int ldb,
    const float* __restrict__ sA, const float* __restrict__ sB,
    int nk, float alpha, float* __restrict__ Cf, int ldc)
{
    extern __shared__ char smem[];
    const uint32_t sbase = smem_u32(smem);
    const int tid = threadIdx.x, lane = tid & 31, wid = tid >> 5;
    const int wm = (wid & 1) * 64;     // warp row offset (2 warps over M)
    const int wn = (wid >> 1) * 32;    // warp col offset (4 warps over N)

    auto load_stage = [&](int s, int buf) {
        const size_t k0 = (size_t)s * BKB;
        const uint32_t sb = sbase + buf * STG;
#pragma unroll
        for (int i = 0; i < 2; i++) {
            int f = tid + i * 256;              // 0..511
            int r = f >> 2, c = (f & 3) * 16;   // 128 rows x 4 chunks of 16 B
            uint32_t so = r * ASTR + c;
            CP_ASYNC16(sb + so,             (const char*)A1 + (size_t)r * lda + k0 + c);
            CP_ASYNC16(sb + ATILE + so,     (const char*)A2 + (size_t)r * lda + k0 + c);
            CP_ASYNC16(sb + 2 * ATILE + so, (const char*)B1 + (size_t)r * ldb + k0 + c);
            CP_ASYNC16(sb + 3 * ATILE + so, (const char*)B2 + (size_t)r * ldb + k0 + c);
        }
        CP_COMMIT();
    };

    int accM[4][4][4], accL[4][4][4];
#pragma unroll
    for (int i = 0; i < 4; i++)
#pragma unroll
        for (int j = 0; j < 4; j++)
#pragma unroll
            for (int t = 0; t < 4; t++) { accM[i][j][t] = 0; accL[i][j][t] = 0; }

    // ldmatrix per-lane address pieces (same pattern as fp16 k16: 32 B rows)
    const int arow = (lane & 7) + ((lane >> 3) & 1) * 8;
    const int asel = ((lane >> 4) & 1) * 16;
    const int brow = (lane & 7) + ((lane >> 4) & 1) * 8;
    const int bsel = ((lane >> 3) & 1) * 16;

    load_stage(0, 0);
    if (nk > 1) load_stage(1, 1);

    for (int s = 0; s < nk; s++) {
        if (s + 2 < nk) load_stage(s + 2, (s + 2) % 3);
        const int ahead = (nk - 1 - s > 2) ? 2 : (nk - 1 - s);
        if (ahead == 2)      asm volatile("cp.async.wait_group 2;" ::: "memory");
        else if (ahead == 1) asm volatile("cp.async.wait_group 1;" ::: "memory");
        else                 asm volatile("cp.async.wait_group 0;" ::: "memory");
        __syncthreads();

        const uint32_t sb = sbase + (s % 3) * STG;
#pragma unroll
        for (int kk = 0; kk < 2; kk++) {          // two k32 steps per stage
            uint32_t a1[4][4], a2[4][4];
#pragma unroll
            for (int mt = 0; mt < 4; mt++) {
                uint32_t ad = sb + (wm + mt * 16 + arow) * ASTR + kk * 32 + asel;
                ldm4(a1[mt], ad);
                ldm4(a2[mt], ad + ATILE);
            }
#pragma unroll
            for (int np = 0; np < 2; np++) {
                uint32_t b1[4], b2[4];
                uint32_t bd = sb + 2 * ATILE
                            + (wn + np * 16 + brow) * ASTR + kk * 32 + bsel;
                ldm4(b1, bd);
                ldm4(b2, bd + ATILE);
                // pass-grouped: long dependency distance per accumulator
#pragma unroll
                for (int mt = 0; mt < 4; mt++) {          // d1·d1 -> accM
                    mma_s8(accM[mt][np * 2],     a1[mt], b1);
                    mma_s8(accM[mt][np * 2 + 1], a1[mt], b1 + 2);
                }
#pragma unroll
                for (int mt = 0; mt < 4; mt++) {          // d1·d2 -> accL
                    mma_s8(accL[mt][np * 2],     a1[mt], b2);
                    mma_s8(accL[mt][np * 2 + 1], a1[mt], b2 + 2);
                }
#pragma unroll
                for (int mt = 0; mt < 4; mt++) {          // d2·d1 -> accL
                    mma_s8(accL[mt][np * 2],     a2[mt], b1);
                    mma_s8(accL[mt][np * 2 + 1], a2[mt], b1 + 2);
                }
            }
        }
        __syncthreads();
    }

    // Epilogue: c0,c1 -> row m, cols n,n+1; c2,c3 -> row m+8.
    const int er = lane >> 2, ec = (lane & 3) * 2;
#pragma unroll
    for (int mt = 0; mt < 4; mt++) {
        const int m = wm + mt * 16 + er;
        const float sa0 = sA[m] * alpha, sa1 = sA[m + 8] * alpha;
#pragma unroll
        for (int nt = 0; nt < 4; nt++) {
            const int n = wn + nt * 8 + ec;
            const float sb0 = sB[n], sb1 = sB[n + 1];
            const int* M = accM[mt][nt];
            const int* L = accL[mt][nt];
            float c0 = sa0 * sb0 * ((float)M[0] + (float)L[0] * INV254);
            float c1 = sa0 * sb1 * ((float)M[1] + (float)L[1] * INV254);
            float c2 = sa1 * sb0 * ((float)M[2] + (float)L[2] * INV254);
            float c3 = sa1 * sb1 * ((float)M[3] + (float)L[3] * INV254);
            *(float2*)(Cf + (size_t)m * ldc + n)       = make_float2(c0, c1);
            *(float2*)(Cf + (size_t)(m + 8) * ldc + n) = make_float2(c2, c3);
        }
    }
}

// ---------------------------------------------------------------------------
// Quantization: one block per row, cols = DIM. sel: 0=X, 1..3=W slot,
// 4=Q (src g_qf), 5=K (src g_kf).
// ---------------------------------------------------------------------------
__global__ void __launch_bounds__(256)
quant_rows(const float* __restrict__ ext_src, int sel)
{
    const int row = blockIdx.x, tid = threadIdx.x;
    const float* src;
    int8_t *d1, *d2; float* sc; int srow;
    if (sel == 0)      { src = ext_src; d1 = g_x1; d2 = g_x2; sc = g_sx; srow = row; }
    else if (sel <= 3) { src = ext_src; srow = (sel - 1) * DIM + row;
                         d1 = g_w1; d2 = g_w2; sc = g_sw; }
    else if (sel == 4) { src = g_qf; d1 = g_q1; d2 = g_q2; sc = g_sq; srow = row; }
    else               { src = g_kf; d1 = g_k1; d2 = g_k2; sc = g_sk; srow = row; }
    const float4* s4 = (const float4*)(src + (size_t)row * DIM);

    __shared__ float red[256];
    float4 v = s4[tid];   // DIM/4 == 256 == blockDim
    float m = fmaxf(fmaxf(fabsf(v.x), fabsf(v.y)), fmaxf(fabsf(v.z), fabsf(v.w)));
    red[tid] = m; __syncthreads();
    for (int st = 128; st > 0; st >>= 1) {
        if (tid < st) red[tid] = fmaxf(red[tid], red[tid + st]);
        __syncthreads();
    }
    m = red[0];
    const float inv = (m > 0.0f) ? 127.0f / m : 0.0f;
    if (tid == 0) sc[srow] = (m > 0.0f) ? m / 127.0f : 0.0f;

    char4 o1, o2;
    quant2(v.x, inv, o1.x, o2.x);
    quant2(v.y, inv, o1.y, o2.y);
    quant2(v.z, inv, o1.z, o2.z);
    quant2(v.w, inv, o1.w, o2.w);
    ((char4*)(d1 + (size_t)srow * DIM))[tid] = o1;
    ((char4*)(d2 + (size_t)srow * DIM))[tid] = o2;
}

// ---------------------------------------------------------------------------
// V column-max (per (b, o)), then transpose+quantize V into [b][o][n] digits
// ---------------------------------------------------------------------------
__global__ void zero_sv_kernel()
{
    int i = blockIdx.x * 256 + threadIdx.x;
    if (i < BATCH * DIM) g_svu[i] = 0;
}
__global__ void __launch_bounds__(256)
colmax_v_kernel()   // grid (DIM/256, SEQ/128, BATCH)
{
    const int b = blockIdx.z, o = blockIdx.x * 256 + threadIdx.x;
    const int n0 = blockIdx.y * 128;
    const float* v = g_vf + ((size_t)b * SEQ + n0) * DIM + o;
    float m = 0.0f;
#pragma unroll 4
    for (int i = 0; i < 128; i++) m = fmaxf(m, fabsf(v[(size_t)i * DIM]));
    atomicMax(&g_svu[b * DIM + o], __float_as_uint(m));
}
__global__ void sv_finalize_kernel()
{
    int i = blockIdx.x * 256 + threadIdx.x;
    if (i < BATCH * DIM) {
        float m = __uint_as_float(g_svu[i]);
        g_sv[i] = (m > 0.0f) ? m / 127.0f : 0.0f;
    }
}
__global__ void vtrans_quant_kernel()   // grid (DIM/32, SEQ/32, BATCH), 32x8
{
    __shared__ float t[32][33];
    const int b = blockIdx.z, o0 = blockIdx.x * 32, n0 = blockIdx.y * 32;
    const int tx = threadIdx.x, ty = threadIdx.y;
    const float* src = g_vf + (size_t)b * SEQ * DIM;
#pragma unroll
    for (int i = 0; i < 4; i++)
        t[ty + i * 8][tx] = src[(size_t)(n0 + ty + i * 8) * DIM + o0 + tx];
    __syncthreads();
#pragma unroll
    for (int i = 0; i < 4; i++) {
        const int o = o0 + ty + i * 8;
        float mx = __uint_as_float(g_svu[b * DIM + o]);
        float inv = (mx > 0.0f) ? 127.0f / mx : 0.0f;
        int8_t d1, d2;
        quant2(t[tx][ty + i * 8], inv, d1, d2);
        size_t off = ((size_t)b * DIM + o) * SEQ + n0 + tx;
        g_vt1[off] = d1; g_vt2[off] = d2;
    }
}

// ---------------------------------------------------------------------------
// GEMM kernels
// ---------------------------------------------------------------------------
__global__ void __launch_bounds__(256, 1)
qkv_kernel()   // {Q,K,V} = X @ W^T -> fp32
{
    const int bx = blockIdx.x, by = blockIdx.y, z = blockIdx.z;
    const size_t ao = (size_t)by * 128 * DIM;
    const size_t wo = ((size_t)z * DIM + (size_t)bx * 128) * DIM;
    float* Cf = (z == 0 ? g_qf : z == 1 ? g_kf : g_vf)
                + (size_t)by * 128 * DIM + (size_t)bx * 128;
    imma_core(g_x1 + ao, g_x2 + ao, DIM,
              g_w1 + wo, g_w2 + wo, DIM,
              g_sx + by * 128, g_sw + z * DIM + bx * 128,
              DIM / BKB, 1.0f, Cf, DIM);
}

__global__ void __launch_bounds__(256, 1)
scores_kernel()   // S = (1/32) Q K^T, masked blocks skipped
{
    const int bx = blockIdx.x, by = blockIdx.y, b = blockIdx.z;
    if (bx > by) return;
    const size_t ao = ((size_t)b * SEQ + (size_t)by * 128) * DIM;
    const size_t bo = ((size_t)b * SEQ + (size_t)bx * 128) * DIM;
    float* Cf = g_s + (size_t)b * SEQ * SEQ + (size_t)by * 128 * SEQ
                    + (size_t)bx * 128;
    imma_core(g_q1 + ao, g_q2 + ao, DIM,
              g_k1 + bo, g_k2 + bo, DIM,
              g_sq + b * SEQ + by * 128, g_sk + b * SEQ + bx * 128,
              DIM / BKB, 0.03125f, Cf, SEQ);
}

__global__ void __launch_bounds__(256)
softmax_kernel()   // causal softmax; emit P digits (scale inv/127), zero-pad
{
    const int row = blockIdx.x;
    const int i   = row & (SEQ - 1);
    const size_t ro = (size_t)row * SEQ;
    const float4* s4 = (const float4*)(g_s + ro);
    const int len = i + 1, tid = threadIdx.x;
    const int n4 = (((i >> 7) + 1) << 7) >> 2;   // lenPad / 4

    __shared__ float red[256];

    float m = -1e30f;
    for (int j4 = tid; j4 < n4; j4 += 256) {
        float4 v = s4[j4];
        int base = j4 * 4;
        v.x = (base + 0 < len) ? v.x : -1e30f;
        v.y = (base + 1 < len) ? v.y : -1e30f;
        v.z = (base + 2 < len) ? v.z : -1e30f;
        v.w = (base + 3 < len) ? v.w : -1e30f;
        m = fmaxf(m, fmaxf(fmaxf(v.x, v.y), fmaxf(v.z, v.w)));
    }
    red[tid] = m; __syncthreads();
    for (int st = 128; st > 0; st >>= 1) {
        if (tid < st) red[tid] = fmaxf(red[tid], red[tid + st]);
        __syncthreads();
    }
    m = red[0]; __syncthreads();

    float sum = 0.0f;
    for (int j4 = tid; j4 < n4; j4 += 256) {
        float4 v = s4[j4];
        int base = j4 * 4;
        sum += (base + 0 < len) ? __expf(v.x - m) : 0.0f;
        sum += (base + 1 < len) ? __expf(v.y - m) : 0.0f;
        sum += (base + 2 < len) ? __expf(v.z - m) : 0.0f;
        sum += (base + 3 < len) ? __expf(v.w - m) : 0.0f;
    }
    red[tid] = sum; __syncthreads();
    for (int st = 128; st > 0; st >>= 1) {
        if (tid < st) red[tid] += red[tid + st];
        __syncthreads();
    }
    const float inv = 1.0f / red[0];
    if (tid == 0) g_sp[row] = inv * (1.0f / 127.0f);

    // digits of e = exp(s-m) in [0,1]: p = (inv/127)*(d1 + d2/254)
    char4* p1 = (char4*)(g_p1 + ro);
    char4* p2 = (char4*)(g_p2 + ro);
    for (int j4 = tid; j4 < n4; j4 += 256) {
        float4 v = s4[j4];
        int base = j4 * 4;
        float e0 = (base + 0 < len) ? __expf(v.x - m) : 0.0f;
        float e1 = (base + 1 < len) ? __expf(v.y - m) : 0.0f;
        float e2 = (base + 2 < len) ? __expf(v.z - m) : 0.0f;
        float e3 = (base + 3 < len) ? __expf(v.w - m) : 0.0f;
        char4 o1, o2;
        quant2(e0, 127.0f, o1.x, o2.x);
        quant2(e1, 127.0f, o1.y, o2.y);
        quant2(e2, 127.0f, o1.z, o2.z);
        quant2(e3, 127.0f, o1.w, o2.w);
        p1[j4] = o1; p2[j4] = o2;
    }
}

__global__ void __launch_bounds__(256, 1)
pv_kernel(float* __restrict__ out)   // O = P @ V, causal-truncated
{
    const int bx = blockIdx.x, by = blockIdx.y, b = blockIdx.z;
    const size_t ao = ((size_t)b * SEQ + (size_t)by * 128) * SEQ;
    const size_t bo = ((size_t)b * DIM + (size_t)bx * 128) * SEQ;
    float* Cf = out + ((size_t)b * SEQ + (size_t)by * 128) * DIM
                    + (size_t)bx * 128;
    imma_core(g_p1 + ao, g_p2 + ao, SEQ,
              g_vt1 + bo, g_vt2 + bo, SEQ,
              g_sp + b * SEQ + by * 128, g_sv + b * DIM + bx * 128,
              (by + 1) * 2, 1.0f, Cf, DIM);
}

// ---------------------------------------------------------------------------
// Launch
// ---------------------------------------------------------------------------
extern "C" void kernel_launch(void* const* d_in, const int* in_sizes, int n_in,
                              void* d_out, int out_size)
{
    const float* x  = (const float*)d_in[0];
    const float* Wq = (const float*)d_in[1];
    const float* Wk = (const float*)d_in[2];
    const float* Wv = (const float*)d_in[3];
    float* out = (float*)d_out;

    cudaFuncSetAttribute(qkv_kernel,
        cudaFuncAttributeMaxDynamicSharedMemorySize, SMEM_SZ);
    cudaFuncSetAttribute(scores_kernel,
        cudaFuncAttributeMaxDynamicSharedMemorySize, SMEM_SZ);
    cudaFuncSetAttribute(pv_kernel,
        cudaFuncAttributeMaxDynamicSharedMemorySize, SMEM_SZ);

    // Quantize inputs
    quant_rows<<<ROWS_TOT, 256>>>(x, 0);
    quant_rows<<<DIM, 256>>>(Wq, 1);
    quant_rows<<<DIM, 256>>>(Wk, 2);
    quant_rows<<<DIM, 256>>>(Wv, 3);

    // QKV projections (fp32 out)
    dim3 gq(DIM / 128, ROWS_TOT / 128, 3);
    qkv_kernel<<<gq, 256, SMEM_SZ>>>();

    // Re-quantize Q, K; quantize+transpose V
    quant_rows<<<ROWS_TOT, 256>>>(nullptr, 4);
    quant_rows<<<ROWS_TOT, 256>>>(nullptr, 5);
    zero_sv_kernel<<<(BATCH * DIM) / 256, 256>>>();
    dim3 gc(DIM / 256, SEQ / 128, BATCH);
    colmax_v_kernel<<<gc, 256>>>();
    sv_finalize_kernel<<<(BATCH * DIM) / 256, 256>>>();
    dim3 gt(DIM / 32, SEQ / 32, BATCH);
    vtrans_quant_kernel<<<gt, dim3(32, 8)>>>();

    // Scores (causal block-skip)
    dim3 gs(SEQ / 128, SEQ / 128, BATCH);
    scores_kernel<<<gs, 256, SMEM_SZ>>>();

    // Softmax -> P digits
    softmax_kernel<<<BATCH * SEQ, 256>>>();

    // O = P @ V
    dim3 gp(DIM / 128, SEQ / 128, BATCH);
    pv_kernel<<<gp, 256, SMEM_SZ>>>(out);
}